// round 3
// baseline (speedup 1.0000x reference)
#include <cuda_runtime.h>
#include <math.h>

// AnomalyAttention: B=2, L=2048, H=8, E=64, band |i-j| <= 63.
// out = concat( V [B,L,H,E] f32 , series [B,H,L,L] f32 ).

#define BN 2
#define HN 8
#define LN 2048
#define EN 64
#define RT 32          // rows per block
#define KROWS 160      // padded K/V rows in smem (max span 158, +pair tail)
#define KSTR 68        // row stride: mult of 4 (float4) ; 68%32=4 -> LDS.128 conflict-free
#define SPAD 128       // Ss row stride (max warp span 128)

typedef unsigned long long u64;

__device__ __forceinline__ u64 fma2(u64 a, u64 b, u64 c) {
    u64 d;
    asm("fma.rn.f32x2 %0, %1, %2, %3;" : "=l"(d) : "l"(a), "l"(b), "l"(c));
    return d;
}
__device__ __forceinline__ u64 pack2(float lo, float hi) {
    u64 d;
    asm("mov.b64 %0, {%1, %2};" : "=l"(d) : "f"(lo), "f"(hi));
    return d;
}
__device__ __forceinline__ float2 unpack2(u64 v) {
    float2 r;
    asm("mov.b64 {%0, %1}, %2;" : "=f"(r.x), "=f"(r.y) : "l"(v));
    return r;
}

__global__ __launch_bounds__(512, 2)
void anomaly_attn_kernel(const float* __restrict__ Q,
                         const float* __restrict__ K,
                         const float* __restrict__ V,
                         float* __restrict__ out)
{
    extern __shared__ float sm[];
    float* Qs = sm;                          // RT    * KSTR
    float* Ks = Qs + RT * KSTR;              // KROWS * KSTR
    float* Vs = Ks + KROWS * KSTR;           // KROWS * KSTR
    float* Ss = Vs + KROWS * KSTR;           // RT    * SPAD

    const int bid = blockIdx.x;
    const int t   = bid & 63;           // 64 row tiles
    const int h   = (bid >> 6) & 7;
    const int b   = bid >> 9;
    const int i0  = t * RT;
    const int jlo = max(0, i0 - 63);
    const int jhi = min(LN - 1, i0 + RT + 62);
    const int span = jhi - jlo + 1;              // <= 158

    const int tid  = threadIdx.x;
    const int lane = tid & 31;
    const int w    = tid >> 5;          // 16 warps, 2 rows each

    // ---- zero score buffer ----
    for (int i = tid; i < RT * SPAD; i += 512) Ss[i] = 0.0f;

    // ---- cooperative loads: float4 global -> STS.128, zero-pad K/V ----
    {
        const int e4 = (tid & 15) * 4;
        const int r0 = tid >> 4;            // 0..31
        // Q: one float4 per thread
        *(float4*)(Qs + r0 * KSTR + e4) =
            *(const float4*)&Q[(((size_t)b * LN + (i0 + r0)) * HN + h) * EN + e4];
#pragma unroll
        for (int r = r0; r < KROWS; r += 32) {
            float4 kv = make_float4(0.f, 0.f, 0.f, 0.f);
            float4 vv = make_float4(0.f, 0.f, 0.f, 0.f);
            if (r < span) {
                const size_t g = (((size_t)b * LN + (jlo + r)) * HN + h) * EN + e4;
                kv = *(const float4*)&K[g];
                vv = *(const float4*)&V[g];
            }
            *(float4*)(Ks + r * KSTR + e4) = kv;
            *(float4*)(Vs + r * KSTR + e4) = vv;
        }
    }
    __syncthreads();

    // ---- per-warp geometry: 2 rows ----
    const int ga    = 2 * w;
    const int gia   = i0 + ga;
    const int g_lo  = max(0, gia - 63) - jlo;           // first K/V row
    const int g_hi  = min(LN - 1, gia + 64) - jlo;      // last valid row
    const int spanw = g_hi - g_lo;                      // <= 127
    const int jbase = jlo + g_lo;

    const float scale = 0.125f;

    // ---- GEMM1 (f32x2, LDS.128): scores[2][4] ----
    u64 acc[2][4];
#pragma unroll
    for (int r = 0; r < 2; r++)
#pragma unroll
        for (int s = 0; s < 4; s++) acc[r][s] = 0ull;

    const float4* kp[4];
#pragma unroll
    for (int s = 0; s < 4; s++) {
        const int row = min(g_lo + lane + 32 * s, KROWS - 1);  // garbage lanes masked later
        kp[s] = (const float4*)(Ks + row * KSTR);
    }
    const float4* qp0 = (const float4*)(Qs + (ga + 0) * KSTR);
    const float4* qp1 = (const float4*)(Qs + (ga + 1) * KSTR);

#pragma unroll 4
    for (int e4 = 0; e4 < EN / 4; e4++) {
        const float4 q0f = qp0[e4];
        const float4 q1f = qp1[e4];
        const u64 q0a = pack2(q0f.x, q0f.y);
        const u64 q0b = pack2(q0f.z, q0f.w);
        const u64 q1a = pack2(q1f.x, q1f.y);
        const u64 q1b = pack2(q1f.z, q1f.w);
#pragma unroll
        for (int s = 0; s < 4; s++) {
            const float4 kf = kp[s][e4];
            const u64 ka = pack2(kf.x, kf.y);
            const u64 kb = pack2(kf.z, kf.w);
            acc[0][s] = fma2(q0a, ka, acc[0][s]);
            acc[0][s] = fma2(q0b, kb, acc[0][s]);
            acc[1][s] = fma2(q1a, ka, acc[1][s]);
            acc[1][s] = fma2(q1b, kb, acc[1][s]);
        }
    }

    float sc[2][4];
#pragma unroll
    for (int r = 0; r < 2; r++)
#pragma unroll
        for (int s = 0; s < 4; s++) {
            const float2 a = unpack2(acc[r][s]);
            sc[r][s] = (a.x + a.y) * scale;
        }

    // ---- row max ----
    float mx[2] = { -INFINITY, -INFINITY };
#pragma unroll
    for (int s = 0; s < 4; s++) {
        const int jj = lane + 32 * s;
        const int j  = jbase + jj;
#pragma unroll
        for (int r = 0; r < 2; r++) {
            const int gi = gia + r;
            const bool c = (jj <= spanw) && ((unsigned)(j - gi + 63) <= 126u);
            if (c) mx[r] = fmaxf(mx[r], sc[r][s]);
        }
    }
#pragma unroll
    for (int off = 16; off > 0; off >>= 1)
#pragma unroll
        for (int r = 0; r < 2; r++)
            mx[r] = fmaxf(mx[r], __shfl_xor_sync(0xffffffffu, mx[r], off));

    // ---- exp + sum; unnormalized p -> Ss ----
    float sum[2] = { 0.f, 0.f };
#pragma unroll
    for (int s = 0; s < 4; s++) {
        const int jj = lane + 32 * s;
        const int j  = jbase + jj;
#pragma unroll
        for (int r = 0; r < 2; r++) {
            const int gi = gia + r;
            const bool c = (jj <= spanw) && ((unsigned)(j - gi + 63) <= 126u);
            if (c) {
                const float p = __expf(sc[r][s] - mx[r]);
                sum[r] += p;
                Ss[(ga + r) * SPAD + jj] = p;
            }
        }
    }
#pragma unroll
    for (int off = 16; off > 0; off >>= 1)
#pragma unroll
        for (int r = 0; r < 2; r++)
            sum[r] += __shfl_xor_sync(0xffffffffu, sum[r], off);

    float rinv[2];
#pragma unroll
    for (int r = 0; r < 2; r++) rinv[r] = 1.0f / sum[r];

    __syncwarp();

    // ---- series: bare zero STG.128 outside band, selects inside ----
    float* series = out + (size_t)BN * LN * HN * EN;
#pragma unroll
    for (int r = 0; r < 2; r++) {
        const int gi  = gia + r;
        const float rv = rinv[r];
        const int c_lo = max(0, gi - 63) >> 2;
        const int c_hi = min(LN - 1, gi + 63) >> 2;
        const float* srow = Ss + (ga + r) * SPAD;
        float4* orow = (float4*)(series + ((size_t)((b * HN + h) * LN) + gi) * (size_t)LN);
        for (int c = lane; c < LN / 4; c += 32) {
            float4 vv = make_float4(0.f, 0.f, 0.f, 0.f);
            if (c >= c_lo && c <= c_hi) {
                const int j0 = 4 * c;
#pragma unroll
                for (int u = 0; u < 4; u++) {
                    const int j = j0 + u;
                    const bool cc = (unsigned)(j - gi + 63) <= 126u;
                    const float val = cc ? srow[j - jbase] * rv : 0.0f;
                    if (u == 0) vv.x = val;
                    else if (u == 1) vv.y = val;
                    else if (u == 2) vv.z = val;
                    else vv.w = val;
                }
            }
            __stcs(orow + c, vv);
        }
    }

    // ---- GEMM2 (f32x2 over j-pairs): V_out[2][64] ----
    u64 a0[2], a1[2];
#pragma unroll
    for (int r = 0; r < 2; r++) { a0[r] = 0ull; a1[r] = 0ull; }

    const int niter = (spanw + 2) >> 1;    // tail reads zero-padded Ss/Vs
#pragma unroll 2
    for (int it = 0; it < niter; it++) {
        const int jj = 2 * it;
        const int rv0 = g_lo + jj;
        const int rv1 = rv0 + 1;
        const float va0 = Vs[rv0 * KSTR + lane];
        const float vb0 = Vs[rv0 * KSTR + 32 + lane];
        const float va1 = Vs[rv1 * KSTR + lane];
        const float vb1 = Vs[rv1 * KSTR + 32 + lane];
        const u64 vpa = pack2(va0, va1);
        const u64 vpb = pack2(vb0, vb1);
#pragma unroll
        for (int r = 0; r < 2; r++) {
            const float2 pp = *(const float2*)(Ss + (ga + r) * SPAD + jj);
            const u64 pk = pack2(pp.x, pp.y);
            a0[r] = fma2(pk, vpa, a0[r]);
            a1[r] = fma2(pk, vpb, a1[r]);
        }
    }
#pragma unroll
    for (int r = 0; r < 2; r++) {
        const int gi = gia + r;
        const size_t o = (((size_t)b * LN + gi) * HN + h) * EN;
        const float2 x0 = unpack2(a0[r]);
        const float2 x1 = unpack2(a1[r]);
        out[o + lane]      = (x0.x + x0.y) * rinv[r];
        out[o + 32 + lane] = (x1.x + x1.y) * rinv[r];
    }
}

extern "C" void kernel_launch(void* const* d_in, const int* in_sizes, int n_in,
                              void* d_out, int out_size) {
    const float* Q = (const float*)d_in[0];
    const float* K = (const float*)d_in[1];
    const float* V = (const float*)d_in[2];
    float* out = (float*)d_out;

    const int smem_bytes = (RT * KSTR + 2 * KROWS * KSTR + RT * SPAD) * (int)sizeof(float);
    cudaFuncSetAttribute(anomaly_attn_kernel,
                         cudaFuncAttributeMaxDynamicSharedMemorySize, smem_bytes);

    dim3 grid(BN * HN * (LN / RT));   // 1024 blocks
    dim3 block(512);
    anomaly_attn_kernel<<<grid, block, smem_bytes>>>(Q, K, V, out);
}